// round 13
// baseline (speedup 1.0000x reference)
#include <cuda_runtime.h>
#include <cuda_bf16.h>
#include <cuda_fp8.h>
#include <cstdint>

// ============================================================================
// x [M,K] fp32 (bf16-valued), w [N,K] fp32 -> out [M,N] fp32
//   = bf16_round((e4m3(sparsify24(x)) @ e4m3(w)^T) * xs * ws)
// FP8 mma.sync core; quant scratch stored in TILED+SWIZZLED layout so the
// GEMM loads each stage with TWO cp.async.bulk (UBLKCP) instead of ~1500
// cp.async (which was the measured issue-rate bottleneck: 8 cyc/LDGSTS).
// ============================================================================
#define DIM_M 8192
#define DIM_K 4096
#define DIM_N 4096

// A blocks: [tm 0..63][ks 0..63] of 128 rows x 64 B  (swizzled), 8 KB each
// B blocks: [tn 0..15][ks 0..63] of 256 rows x 64 B  (swizzled), 16 KB each
__device__ __align__(1024) uint8_t g_xq[(size_t)DIM_M * DIM_K];   // 32 MB
__device__ __align__(1024) uint8_t g_wq[(size_t)DIM_N * DIM_K];   // 16 MB
__device__ float g_xs[DIM_M];
__device__ float g_ws[DIM_N];

// ============================================================================
// PTX helpers (plain-target)
// ============================================================================
__device__ __forceinline__ uint32_t smem_to_u32(const void* p) {
    uint32_t a;
    asm("{ .reg .u64 t; cvta.to.shared.u64 t, %1; cvt.u32.u64 %0, t; }"
        : "=r"(a) : "l"(p));
    return a;
}

#define MBARRIER_INIT(addr, cnt) \
    asm volatile("mbarrier.init.shared.b64 [%0], %1;" \
        :: "r"((uint32_t)(addr)), "r"((uint32_t)(cnt)) : "memory")

#define MBARRIER_EXPECT_TX(addr, bytes) \
    asm volatile("mbarrier.arrive.expect_tx.shared.b64 _, [%0], %1;" \
        :: "r"((uint32_t)(addr)), "r"((uint32_t)(bytes)) : "memory")

#define MBARRIER_WAIT_PARITY(mbar_smem_addr, phase_parity) do { \
    uint32_t _mbar = (uint32_t)(mbar_smem_addr); \
    uint32_t _parity = (uint32_t)(phase_parity); \
    uint32_t _done; \
    asm volatile( \
        "{\n\t.reg .pred p;\n\t" \
        "mbarrier.try_wait.parity.acquire.cta.shared::cta.b64 p, [%1], %2;\n\t" \
        "selp.b32 %0, 1, 0, p;\n\t}" \
        : "=r"(_done) : "r"(_mbar), "r"(_parity) : "memory"); \
    if (!_done) { \
        asm volatile( \
            "{\n\t.reg .pred P1;\n\t" \
            "WAIT_LOOP_%=:\n\t" \
            "mbarrier.try_wait.parity.acquire.cta.shared::cta.b64 P1, [%0], %1, 0x989680;\n\t" \
            "@P1 bra.uni WAIT_DONE_%=;\n\t" \
            "bra.uni WAIT_LOOP_%=;\n\t" \
            "WAIT_DONE_%=:\n\t}" \
            :: "r"(_mbar), "r"(_parity) : "memory"); \
    } \
} while(0)

#define CP_BULK(dst, src, bytes, mbar) \
    asm volatile( \
        "cp.async.bulk.shared::cta.global.mbarrier::complete_tx::bytes " \
        "[%0], [%1], %2, [%3];" \
        :: "r"((uint32_t)(dst)), "l"(src), "r"((uint32_t)(bytes)), \
           "r"((uint32_t)(mbar)) : "memory")

__device__ __forceinline__ void ldsm_x4(uint32_t* r, uint32_t addr) {
    asm volatile("ldmatrix.sync.aligned.m8n8.x4.shared.b16 {%0,%1,%2,%3}, [%4];\n"
                 : "=r"(r[0]), "=r"(r[1]), "=r"(r[2]), "=r"(r[3]) : "r"(addr));
}

// D += A(e4m3, m16 x k32, row) * B(e4m3, k32 x n8, col) ; f32 accum
__device__ __forceinline__ void mma_e4m3(float* c, const uint32_t* a,
                                         uint32_t b0, uint32_t b1) {
    asm volatile(
        "mma.sync.aligned.m16n8k32.row.col.f32.e4m3.e4m3.f32 "
        "{%0,%1,%2,%3}, {%4,%5,%6,%7}, {%8,%9}, {%0,%1,%2,%3};\n"
        : "+f"(c[0]), "+f"(c[1]), "+f"(c[2]), "+f"(c[3])
        : "r"(a[0]), "r"(a[1]), "r"(a[2]), "r"(a[3]), "r"(b0), "r"(b1));
}

__device__ __forceinline__ float round_bf16(float v) {
    return __bfloat162float(__float2bfloat16(v));
}

__device__ __forceinline__ uint8_t quant_e4m3(float v) {
    return (uint8_t)__nv_cvt_float_to_fp8(v, __NV_SATFINITE, __NV_E4M3);
}

// swizzled word index inside a [rows x 64B] block for (rr, gi-within-row)
//   w = word 0..15 in the row; chunk c = w>>2; c' = c ^ ((rr>>1)&3)
__device__ __forceinline__ uint32_t swz_word(int rr, int w) {
    int c = w >> 2;
    int cs = c ^ ((rr >> 1) & 3);
    return (uint32_t)(rr * 16 + cs * 4 + (w & 3));
}

// ============================================================================
// Kernel 1: rowwise e4m3 quant of weight [N,K] -> tiled/swizzled g_wq
// ============================================================================
__global__ __launch_bounds__(128) void quant_w_kernel(const float* __restrict__ w) {
    int row = blockIdx.x;
    int t = threadIdx.x;
    const float* rp = w + (size_t)row * DIM_K;

    float v[8][4];
    float amax = 0.0f;
#pragma unroll
    for (int i = 0; i < 8; i++) {
        int gi = t + i * 128;
        float4 raw = *reinterpret_cast<const float4*>(rp + 4 * gi);
        v[i][0] = raw.x; v[i][1] = raw.y; v[i][2] = raw.z; v[i][3] = raw.w;
#pragma unroll
        for (int j = 0; j < 4; j++) amax = fmaxf(amax, fabsf(v[i][j]));
    }
#pragma unroll
    for (int o = 16; o; o >>= 1) amax = fmaxf(amax, __shfl_xor_sync(0xFFFFFFFFu, amax, o));
    __shared__ float red[4];
    if ((t & 31) == 0) red[t >> 5] = amax;
    __syncthreads();
    float am = fmaxf(fmaxf(red[0], red[1]), fmaxf(red[2], red[3]));
    float scale = __fdiv_rn(fmaxf(am, 1e-12f), 448.0f);

    uint32_t* qbase = reinterpret_cast<uint32_t*>(g_wq);
    int tn = row >> 8, rr = row & 255;
#pragma unroll
    for (int i = 0; i < 8; i++) {
        int gi = t + i * 128;          // k-group (4 bytes)
        uint32_t packed = 0;
#pragma unroll
        for (int j = 0; j < 4; j++)
            packed |= (uint32_t)quant_e4m3(__fdiv_rn(v[i][j], scale)) << (j * 8);
        int ks = gi >> 4, wrd = gi & 15;
        qbase[(uint32_t)(tn * 64 + ks) * 4096 + rr * 0 + ((uint32_t)swz_word(rr, wrd)) +
              (uint32_t)0 * 0 + (uint32_t)(0)] = packed;  // placeholder fixed below
    }
    // NOTE: the line above must index block*(256*16); rewritten correctly:
    // (kept dead to avoid miscompile confusion)
    if (t == 0) g_ws[row] = scale;
}

// correct version (used): separate to keep addressing obvious
__global__ __launch_bounds__(128) void quant_w_kernel2(const float* __restrict__ w) {
    int row = blockIdx.x;
    int t = threadIdx.x;
    const float* rp = w + (size_t)row * DIM_K;

    float v[8][4];
    float amax = 0.0f;
#pragma unroll
    for (int i = 0; i < 8; i++) {
        int gi = t + i * 128;
        float4 raw = *reinterpret_cast<const float4*>(rp + 4 * gi);
        v[i][0] = raw.x; v[i][1] = raw.y; v[i][2] = raw.z; v[i][3] = raw.w;
#pragma unroll
        for (int j = 0; j < 4; j++) amax = fmaxf(amax, fabsf(v[i][j]));
    }
#pragma unroll
    for (int o = 16; o; o >>= 1) amax = fmaxf(amax, __shfl_xor_sync(0xFFFFFFFFu, amax, o));
    __shared__ float red[4];
    if ((t & 31) == 0) red[t >> 5] = amax;
    __syncthreads();
    float am = fmaxf(fmaxf(red[0], red[1]), fmaxf(red[2], red[3]));
    float scale = __fdiv_rn(fmaxf(am, 1e-12f), 448.0f);

    uint32_t* qbase = reinterpret_cast<uint32_t*>(g_wq);
    int tn = row >> 8, rr = row & 255;
#pragma unroll
    for (int i = 0; i < 8; i++) {
        int gi = t + i * 128;
        uint32_t packed = 0;
#pragma unroll
        for (int j = 0; j < 4; j++)
            packed |= (uint32_t)quant_e4m3(__fdiv_rn(v[i][j], scale)) << (j * 8);
        int ks = gi >> 4, wrd = gi & 15;
        // block (tn,ks): 256 rows x 16 words
        qbase[((uint32_t)(tn * 64 + ks)) * (256 * 16) + swz_word(rr, wrd)] = packed;
    }
    if (t == 0) g_ws[row] = scale;
}

// ============================================================================
// Kernel 2: 2:4 sparsify + rowwise e4m3 quant of x [M,K] -> tiled g_xq
// ============================================================================
__global__ __launch_bounds__(128) void quant_x_kernel(const float* __restrict__ x) {
    int row = blockIdx.x;
    int t = threadIdx.x;
    const float* rp = x + (size_t)row * DIM_K;

    float v[8][4];
    float amax = 0.0f;
#pragma unroll
    for (int i = 0; i < 8; i++) {
        int gi = t + i * 128;
        float4 raw = *reinterpret_cast<const float4*>(rp + 4 * gi);
        v[i][0] = raw.x; v[i][1] = raw.y; v[i][2] = raw.z; v[i][3] = raw.w;
#pragma unroll
        for (int j = 0; j < 4; j++) amax = fmaxf(amax, fabsf(v[i][j]));
    }
#pragma unroll
    for (int o = 16; o; o >>= 1) amax = fmaxf(amax, __shfl_xor_sync(0xFFFFFFFFu, amax, o));
    __shared__ float red[4];
    if ((t & 31) == 0) red[t >> 5] = amax;
    __syncthreads();
    float am = fmaxf(fmaxf(red[0], red[1]), fmaxf(red[2], red[3]));
    float scale = __fdiv_rn(fmaxf(am, 1e-12f), 448.0f);

    uint32_t* qbase = reinterpret_cast<uint32_t*>(g_xq);
    int tm = row >> 7, rr = row & 127;
#pragma unroll
    for (int i = 0; i < 8; i++) {
        int gi = t + i * 128;
        float a[4];
#pragma unroll
        for (int j = 0; j < 4; j++) a[j] = fabsf(v[i][j]);
        uint32_t packed = 0;
#pragma unroll
        for (int j = 0; j < 4; j++) {
            int rank = 0;
#pragma unroll
            for (int k = 0; k < 4; k++)
                if (k != j && (a[k] > a[j] || (a[k] == a[j] && k < j))) rank++;
            if (rank < 2)
                packed |= (uint32_t)quant_e4m3(__fdiv_rn(v[i][j], scale)) << (j * 8);
        }
        int ks = gi >> 4, wrd = gi & 15;
        // block (tm,ks): 128 rows x 16 words
        qbase[((uint32_t)(tm * 64 + ks)) * (128 * 16) + swz_word(rr, wrd)] = packed;
    }
    if (t == 0) g_xs[row] = scale;
}

// ============================================================================
// Kernel 3: FP8 GEMM, CTA 128x256, 512 thr (16 warps, 4m x 4n), warp 32x64.
// Stage = one (tm,ks) A block (8KB) + one (tn,ks) B block (16KB) via 2x
// cp.async.bulk; 3 stages; mbarrier full[s]; __syncthreads gives reuse safety.
// ============================================================================
#define TILE_M 128
#define TILE_N 256
#define NKIT   64
#define STAGES 3
#define NTHREADS 512

static constexpr uint32_t A_STG = 128 * 64;                 // 8192
static constexpr uint32_t B_STG = 256 * 64;                 // 16384
static constexpr uint32_t STAGE_BYTES = A_STG + B_STG;      // 24576
static constexpr uint32_t DSMEM_TOTAL = STAGES * STAGE_BYTES; // 73728

__global__ __launch_bounds__(NTHREADS, 1) void gemm_kernel(float* __restrict__ out) {
    extern __shared__ uint8_t dynsmem[];
    __shared__ __align__(8) uint64_t mbar_full[STAGES];
    __shared__ float xs_s[TILE_M];
    __shared__ float ws_s[TILE_N];

    uint32_t sbase = smem_to_u32(dynsmem);
    uint32_t mb = smem_to_u32(mbar_full);
    int tid  = threadIdx.x;
    int wid  = tid >> 5;
    int lane = tid & 31;
    int g    = lane >> 2;
    int tg   = lane & 3;
    int wm = wid >> 2;      // 0..3
    int wn = wid & 3;       // 0..3
    int m0 = wm * 32;
    int n0 = wn * 64;
    int bx = blockIdx.x;    // 0..15 (tile_n index)
    int by = blockIdx.y;    // 0..63 (tile_m index)
    int tile_m = by * TILE_M;
    int tile_n = bx * TILE_N;

    if (tid < TILE_M) xs_s[tid] = g_xs[tile_m + tid];
    if (tid < TILE_N) ws_s[tid] = g_ws[tile_n + tid];

    if (tid == 0) {
#pragma unroll
        for (int s = 0; s < STAGES; s++) MBARRIER_INIT(mb + 8 * s, 1);
    }
    __syncthreads();

    const uint8_t* a_gbase = g_xq + (size_t)by * 64 * A_STG;   // + ks*A_STG
    const uint8_t* b_gbase = g_wq + (size_t)bx * 64 * B_STG;   // + ks*B_STG

    // prologue: fill stages 0,1
    if (tid == 0) {
#pragma unroll
        for (int j = 0; j < STAGES - 1; j++) {
            MBARRIER_EXPECT_TX(mb + 8 * j, STAGE_BYTES);
            CP_BULK(sbase + j * STAGE_BYTES,            a_gbase + (size_t)j * A_STG, A_STG, mb + 8 * j);
            CP_BULK(sbase + j * STAGE_BYTES + A_STG,    b_gbase + (size_t)j * B_STG, B_STG, mb + 8 * j);
        }
    }

    float c[2][8][4];
#pragma unroll
    for (int i = 0; i < 2; i++)
#pragma unroll
        for (int j = 0; j < 8; j++)
#pragma unroll
            for (int e = 0; e < 4; e++) c[i][j][e] = 0.0f;

    // per-lane ldmatrix row components
    int a_row = m0 + (lane & 15);                       // + mt*16
    int a_chunk_lane = (lane >> 4);                     // + 2*kk
    int b_row = n0 + (lane & 7) + ((lane >> 4) << 3);   // + ng*16
    int b_chunk_lane = ((lane >> 3) & 1);               // + 2*kk

    for (int i = 0; i < NKIT; i++) {
        __syncthreads();   // all threads done consuming iter i-1 -> slot reuse safe
        int nxt = i + STAGES - 1;
        if (tid == 0 && nxt < NKIT) {
            int s = nxt % STAGES;
            MBARRIER_EXPECT_TX(mb + 8 * s, STAGE_BYTES);
            CP_BULK(sbase + s * STAGE_BYTES,         a_gbase + (size_t)nxt * A_STG, A_STG, mb + 8 * s);
            CP_BULK(sbase + s * STAGE_BYTES + A_STG, b_gbase + (size_t)nxt * B_STG, B_STG, mb + 8 * s);
        }
        int cs = i % STAGES;
        MBARRIER_WAIT_PARITY(mb + 8 * cs, (i / STAGES) & 1);

        uint32_t a_s = sbase + (uint32_t)cs * STAGE_BYTES;
        uint32_t b_s = a_s + A_STG;

#pragma unroll
        for (int kk = 0; kk < 2; kk++) {
            uint32_t af[2][4], bf[4][4];
#pragma unroll
            for (int mt = 0; mt < 2; mt++) {
                int r = a_row + mt * 16;
                int ch = (2 * kk + a_chunk_lane) ^ ((r >> 1) & 3);
                ldsm_x4(af[mt], a_s + r * 64 + ch * 16);
            }
#pragma unroll
            for (int ng = 0; ng < 4; ng++) {
                int r = b_row + ng * 16;
                int ch = (2 * kk + b_chunk_lane) ^ ((r >> 1) & 3);
                ldsm_x4(bf[ng], b_s + r * 64 + ch * 16);
            }
#pragma unroll
            for (int mt = 0; mt < 2; mt++)
#pragma unroll
                for (int nt = 0; nt < 8; nt++)
                    mma_e4m3(c[mt][nt], af[mt],
                             bf[nt >> 1][(nt & 1) * 2], bf[nt >> 1][(nt & 1) * 2 + 1]);
        }
    }

    // epilogue: scale, round through bf16, store FP32
#pragma unroll
    for (int mt = 0; mt < 2; mt++) {
        int rl = m0 + mt * 16 + g;
        float xs0 = xs_s[rl];
        float xs1 = xs_s[rl + 8];
        size_t gr0 = (size_t)(tile_m + rl) * DIM_N + tile_n;
        size_t gr1 = (size_t)(tile_m + rl + 8) * DIM_N + tile_n;
#pragma unroll
        for (int nt = 0; nt < 8; nt++) {
            int cl = n0 + nt * 8 + tg * 2;
            float w0 = ws_s[cl];
            float w1 = ws_s[cl + 1];
            float* cc = c[mt][nt];
            float2 r0, r1;
            r0.x = round_bf16(__fmul_rn(__fmul_rn(cc[0], xs0), w0));
            r0.y = round_bf16(__fmul_rn(__fmul_rn(cc[1], xs0), w1));
            r1.x = round_bf16(__fmul_rn(__fmul_rn(cc[2], xs1), w0));
            r1.y = round_bf16(__fmul_rn(__fmul_rn(cc[3], xs1), w1));
            *reinterpret_cast<float2*>(out + gr0 + cl) = r0;
            *reinterpret_cast<float2*>(out + gr1 + cl) = r1;
        }
    }
}

// ============================================================================
// Host launch
// ============================================================================
extern "C" void kernel_launch(void* const* d_in, const int* in_sizes, int n_in,
                              void* d_out, int out_size) {
    const float* x;
    const float* w;
    if (in_sizes[0] >= in_sizes[1]) {
        x = (const float*)d_in[0];
        w = (const float*)d_in[1];
    } else {
        x = (const float*)d_in[1];
        w = (const float*)d_in[0];
    }
    float* out = (float*)d_out;

    quant_w_kernel2<<<DIM_N, 128>>>(w);
    quant_x_kernel<<<DIM_M, 128>>>(x);

    cudaFuncSetAttribute(gemm_kernel, cudaFuncAttributeMaxDynamicSharedMemorySize,
                         DSMEM_TOTAL);
    dim3 grid(DIM_N / TILE_N, DIM_M / TILE_M);  // (16, 64)
    gemm_kernel<<<grid, NTHREADS, DSMEM_TOTAL>>>(out);
}

// round 16
// speedup vs baseline: 1.0439x; 1.0439x over previous
#include <cuda_runtime.h>
#include <cuda_bf16.h>
#include <cuda_fp8.h>
#include <cstdint>

// ============================================================================
// x [M,K] fp32 (bf16-valued), w [N,K] fp32 -> out [M,N] fp32
//   = bf16_round((e4m3(sparsify24(x)) @ e4m3(w)^T) * xs * ws)
// Dense FP8 core (mma.sync.m16n8k32.e4m3) — the sparse fp8 path is spec-
// impossible for element-wise 2:4 (pair-wise 4:8 only). KC=128B per stage.
// Dummy first launch aligns ncu capture (-s 5) onto the GEMM kernel.
// ============================================================================
#define DIM_M 8192
#define DIM_K 4096
#define DIM_N 4096

__device__ __align__(1024) uint8_t g_xq[(size_t)DIM_M * DIM_K];   // 32 MB e4m3
__device__ __align__(1024) uint8_t g_wq[(size_t)DIM_N * DIM_K];   // 16 MB e4m3
__device__ float g_xs[DIM_M];
__device__ float g_ws[DIM_N];
__device__ int g_dummy;

// ============================================================================
// PTX helpers (plain-target)
// ============================================================================
__device__ __forceinline__ uint32_t smem_to_u32(const void* p) {
    uint32_t a;
    asm("{ .reg .u64 t; cvta.to.shared.u64 t, %1; cvt.u32.u64 %0, t; }"
        : "=r"(a) : "l"(p));
    return a;
}

__device__ __forceinline__ void cp_async16(uint32_t saddr, const void* gaddr) {
    asm volatile("cp.async.cg.shared.global [%0], [%1], 16;\n"
                 :: "r"(saddr), "l"(gaddr));
}
#define CP_COMMIT() asm volatile("cp.async.commit_group;\n" ::: "memory")
#define CP_WAIT_1() asm volatile("cp.async.wait_group 1;\n" ::: "memory")

__device__ __forceinline__ void ldsm_x4(uint32_t* r, uint32_t addr) {
    asm volatile("ldmatrix.sync.aligned.m8n8.x4.shared.b16 {%0,%1,%2,%3}, [%4];\n"
                 : "=r"(r[0]), "=r"(r[1]), "=r"(r[2]), "=r"(r[3]) : "r"(addr));
}

// D += A(e4m3, m16 x k32, row) * B(e4m3, k32 x n8, col) ; f32 accum
__device__ __forceinline__ void mma_e4m3(float* c, const uint32_t* a,
                                         uint32_t b0, uint32_t b1) {
    asm volatile(
        "mma.sync.aligned.m16n8k32.row.col.f32.e4m3.e4m3.f32 "
        "{%0,%1,%2,%3}, {%4,%5,%6,%7}, {%8,%9}, {%0,%1,%2,%3};\n"
        : "+f"(c[0]), "+f"(c[1]), "+f"(c[2]), "+f"(c[3])
        : "r"(a[0]), "r"(a[1]), "r"(a[2]), "r"(a[3]), "r"(b0), "r"(b1));
}

__device__ __forceinline__ float round_bf16(float v) {
    return __bfloat162float(__float2bfloat16(v));
}

__device__ __forceinline__ uint8_t quant_e4m3(float v) {
    return (uint8_t)__nv_cvt_float_to_fp8(v, __NV_SATFINITE, __NV_E4M3);
}

// ============================================================================
// Kernel 0: dummy (aligns ncu -s 5 capture onto the GEMM launch)
// ============================================================================
__global__ void dummy_kernel() {
    if (threadIdx.x == 0) g_dummy = 1;
}

// ============================================================================
// Kernel 1: rowwise e4m3 quant of weight [N,K] (fp32 in, packed e4m3 out)
// ============================================================================
__global__ __launch_bounds__(128) void quant_w_kernel(const float* __restrict__ w) {
    int row = blockIdx.x;
    int t = threadIdx.x;
    const float* rp = w + (size_t)row * DIM_K;

    float v[8][4];
    float amax = 0.0f;
#pragma unroll
    for (int i = 0; i < 8; i++) {
        int gi = t + i * 128;
        float4 raw = *reinterpret_cast<const float4*>(rp + 4 * gi);
        v[i][0] = raw.x; v[i][1] = raw.y; v[i][2] = raw.z; v[i][3] = raw.w;
#pragma unroll
        for (int j = 0; j < 4; j++) amax = fmaxf(amax, fabsf(v[i][j]));
    }
#pragma unroll
    for (int o = 16; o; o >>= 1) amax = fmaxf(amax, __shfl_xor_sync(0xFFFFFFFFu, amax, o));
    __shared__ float red[4];
    if ((t & 31) == 0) red[t >> 5] = amax;
    __syncthreads();
    float am = fmaxf(fmaxf(red[0], red[1]), fmaxf(red[2], red[3]));
    float scale = __fdiv_rn(fmaxf(am, 1e-12f), 448.0f);

    uint32_t* qp = reinterpret_cast<uint32_t*>(g_wq + (size_t)row * DIM_K);
#pragma unroll
    for (int i = 0; i < 8; i++) {
        int gi = t + i * 128;
        uint32_t packed = 0;
#pragma unroll
        for (int j = 0; j < 4; j++)
            packed |= (uint32_t)quant_e4m3(__fdiv_rn(v[i][j], scale)) << (j * 8);
        qp[gi] = packed;
    }
    if (t == 0) g_ws[row] = scale;
}

// ============================================================================
// Kernel 2: 2:4 sparsify + rowwise e4m3 quant of x [M,K] (fp32 in, packed out)
// ============================================================================
__global__ __launch_bounds__(128) void quant_x_kernel(const float* __restrict__ x) {
    int row = blockIdx.x;
    int t = threadIdx.x;
    const float* rp = x + (size_t)row * DIM_K;

    float v[8][4];
    float amax = 0.0f;
#pragma unroll
    for (int i = 0; i < 8; i++) {
        int gi = t + i * 128;
        float4 raw = *reinterpret_cast<const float4*>(rp + 4 * gi);
        v[i][0] = raw.x; v[i][1] = raw.y; v[i][2] = raw.z; v[i][3] = raw.w;
#pragma unroll
        for (int j = 0; j < 4; j++) amax = fmaxf(amax, fabsf(v[i][j]));
    }
#pragma unroll
    for (int o = 16; o; o >>= 1) amax = fmaxf(amax, __shfl_xor_sync(0xFFFFFFFFu, amax, o));
    __shared__ float red[4];
    if ((t & 31) == 0) red[t >> 5] = amax;
    __syncthreads();
    float am = fmaxf(fmaxf(red[0], red[1]), fmaxf(red[2], red[3]));
    float scale = __fdiv_rn(fmaxf(am, 1e-12f), 448.0f);

    uint32_t* qp = reinterpret_cast<uint32_t*>(g_xq + (size_t)row * DIM_K);
#pragma unroll
    for (int i = 0; i < 8; i++) {
        int gi = t + i * 128;
        float a[4];
#pragma unroll
        for (int j = 0; j < 4; j++) a[j] = fabsf(v[i][j]);
        uint32_t packed = 0;
#pragma unroll
        for (int j = 0; j < 4; j++) {
            int rank = 0;
#pragma unroll
            for (int k = 0; k < 4; k++)
                if (k != j && (a[k] > a[j] || (a[k] == a[j] && k < j))) rank++;
            if (rank < 2)
                packed |= (uint32_t)quant_e4m3(__fdiv_rn(v[i][j], scale)) << (j * 8);
        }
        qp[gi] = packed;
    }
    if (t == 0) g_xs[row] = scale;
}

// ============================================================================
// Kernel 3: FP8 GEMM. CTA 128x256, 512 thr (16 warps, 4m x 4n), warp 32x64.
// K chunk 128 bytes/stage (NKIT=32); 3-stage cp.async; ldmatrix fragments.
// PITCH 144 (=9*16): ldmatrix-aligned; bank-permutation conflict-free.
// ============================================================================
#define TILE_M 128
#define TILE_N 256
#define KC     128
#define NKIT   (DIM_K / KC)   // 32
#define STAGES 3
#define PITCH  144
#define NTHREADS 512

static constexpr uint32_t A_BYTES     = TILE_M * PITCH;            // 18432
static constexpr uint32_t B_BYTES     = TILE_N * PITCH;            // 36864
static constexpr uint32_t STAGE_BYTES = A_BYTES + B_BYTES;         // 55296
static constexpr uint32_t DSMEM_TOTAL = STAGES * STAGE_BYTES;      // 165888

__device__ __forceinline__ void issue_stage(uint32_t stage_base, int kc_byte,
                                            int tile_m, int tile_n, int tid) {
#pragma unroll
    for (int j = 0; j < 6; j++) {
        int id = tid + j * NTHREADS;     // 0..3071 chunks of 16B
        uint32_t saddr;
        const uint8_t* gp;
        if (id < 1024) {                 // A: 128 rows x 8 chunks of 16B
            int row = id >> 3, ch = id & 7;
            saddr = stage_base + row * PITCH + ch * 16;
            gp = g_xq + (size_t)(tile_m + row) * DIM_K + kc_byte + ch * 16;
        } else {                         // B: 256 rows x 8 chunks of 16B
            int id2 = id - 1024;
            int row = id2 >> 3, ch = id2 & 7;
            saddr = stage_base + A_BYTES + row * PITCH + ch * 16;
            gp = g_wq + (size_t)(tile_n + row) * DIM_K + kc_byte + ch * 16;
        }
        cp_async16(saddr, gp);
    }
}

__global__ __launch_bounds__(NTHREADS, 1) void gemm_kernel(float* __restrict__ out) {
    extern __shared__ uint8_t dynsmem[];
    __shared__ float xs_s[TILE_M];
    __shared__ float ws_s[TILE_N];

    uint32_t sbase = smem_to_u32(dynsmem);
    int tid  = threadIdx.x;
    int wid  = tid >> 5;
    int lane = tid & 31;
    int g    = lane >> 2;
    int tg   = lane & 3;
    int wm = wid >> 2;      // 0..3
    int wn = wid & 3;       // 0..3
    int m0 = wm * 32;
    int n0 = wn * 64;
    int tile_m = blockIdx.y * TILE_M;
    int tile_n = blockIdx.x * TILE_N;

    if (tid < TILE_M) xs_s[tid] = g_xs[tile_m + tid];
    if (tid < TILE_N) ws_s[tid] = g_ws[tile_n + tid];

    float c[2][8][4];
#pragma unroll
    for (int i = 0; i < 2; i++)
#pragma unroll
        for (int j = 0; j < 8; j++)
#pragma unroll
            for (int e = 0; e < 4; e++) c[i][j][e] = 0.0f;

#pragma unroll
    for (int s = 0; s < STAGES - 1; s++) {
        issue_stage(sbase + s * STAGE_BYTES, s * KC, tile_m, tile_n, tid);
        CP_COMMIT();
    }

    // ldmatrix lane components (validated R12 mapping)
    int a_row_off = (lane & 15) * PITCH + (lane >> 4) * 16;
    int b_row_off = ((lane & 7) + (lane >> 4) * 8) * PITCH + ((lane >> 3) & 1) * 16;

    for (int i = 0; i < NKIT; i++) {
        CP_WAIT_1();
        __syncthreads();

        uint32_t a_s = sbase + (uint32_t)(i % STAGES) * STAGE_BYTES;
        uint32_t b_s = a_s + A_BYTES;

#pragma unroll
        for (int kk = 0; kk < 4; kk++) {     // four k32 sub-chunks of the 128B stage
            int koff = kk * 32;
            uint32_t af[2][4], bf[4][4];
#pragma unroll
            for (int mt = 0; mt < 2; mt++)
                ldsm_x4(af[mt], a_s + (m0 + mt * 16) * PITCH + koff + a_row_off);
#pragma unroll
            for (int ng = 0; ng < 4; ng++)
                ldsm_x4(bf[ng], b_s + (n0 + ng * 16) * PITCH + koff + b_row_off);
#pragma unroll
            for (int mt = 0; mt < 2; mt++)
#pragma unroll
                for (int nt = 0; nt < 8; nt++)
                    mma_e4m3(c[mt][nt], af[mt],
                             bf[nt >> 1][(nt & 1) * 2], bf[nt >> 1][(nt & 1) * 2 + 1]);
        }

        int nxt = i + STAGES - 1;
        if (nxt < NKIT)
            issue_stage(sbase + (uint32_t)(nxt % STAGES) * STAGE_BYTES,
                        nxt * KC, tile_m, tile_n, tid);
        CP_COMMIT();   // always commit: exact wait_group ledger
    }

    // epilogue: scale, round through bf16, store FP32
#pragma unroll
    for (int mt = 0; mt < 2; mt++) {
        int rl = m0 + mt * 16 + g;
        float xs0 = xs_s[rl];
        float xs1 = xs_s[rl + 8];
        size_t gr0 = (size_t)(tile_m + rl) * DIM_N + tile_n;
        size_t gr1 = (size_t)(tile_m + rl + 8) * DIM_N + tile_n;
#pragma unroll
        for (int nt = 0; nt < 8; nt++) {
            int cl = n0 + nt * 8 + tg * 2;
            float w0 = ws_s[cl];
            float w1 = ws_s[cl + 1];
            float* cc = c[mt][nt];
            float2 r0, r1;
            r0.x = round_bf16(__fmul_rn(__fmul_rn(cc[0], xs0), w0));
            r0.y = round_bf16(__fmul_rn(__fmul_rn(cc[1], xs0), w1));
            r1.x = round_bf16(__fmul_rn(__fmul_rn(cc[2], xs1), w0));
            r1.y = round_bf16(__fmul_rn(__fmul_rn(cc[3], xs1), w1));
            *reinterpret_cast<float2*>(out + gr0 + cl) = r0;
            *reinterpret_cast<float2*>(out + gr1 + cl) = r1;
        }
    }
}

// ============================================================================
// Host launch
// ============================================================================
extern "C" void kernel_launch(void* const* d_in, const int* in_sizes, int n_in,
                              void* d_out, int out_size) {
    const float* x;
    const float* w;
    if (in_sizes[0] >= in_sizes[1]) {
        x = (const float*)d_in[0];
        w = (const float*)d_in[1];
    } else {
        x = (const float*)d_in[1];
        w = (const float*)d_in[0];
    }
    float* out = (float*)d_out;

    dummy_kernel<<<1, 32>>>();           // shifts ncu -s 5 capture onto gemm
    quant_w_kernel<<<DIM_N, 128>>>(w);
    quant_x_kernel<<<DIM_M, 128>>>(x);

    cudaFuncSetAttribute(gemm_kernel, cudaFuncAttributeMaxDynamicSharedMemorySize,
                         DSMEM_TOTAL);
    dim3 grid(DIM_N / TILE_N, DIM_M / TILE_M);  // (16, 64)
    gemm_kernel<<<grid, NTHREADS, DSMEM_TOTAL>>>(out);
}